// round 8
// baseline (speedup 1.0000x reference)
#include <cuda_runtime.h>
#include <stdint.h>

// Problem constants (match reference)
#define HOP        160
#define FFT        1024
#define NUM_LABELS 72
#define BATCH      4
#define TLEN       240000
#define PAD        (FFT / 2)           // 512
#define LPAD       (TLEN + 2 * PAD)    // 241024
#define NOUT       ((LPAD - FFT) / HOP + 1)  // 1501

#define W_RUN          4
#define WARPS_PER_CTA  4
#define BLOCK          (WARPS_PER_CTA * 32)
#define RUNS_PER_B     ((NOUT + W_RUN - 1) / W_RUN)                        // 376
#define CTAS_X         ((RUNS_PER_B + WARPS_PER_CTA - 1) / WARPS_PER_CTA)  // 94

// Interior runs touch only unpadded indices in [0, TLEN): run in [1, 373]
#define RUN_INT_LO 1
#define RUN_INT_HI 373

__device__ __forceinline__ int reflect_idx(int j)
{
    int o = j - PAD;
    if (o < 0) o = -o;
    else if (o >= TLEN) o = 2 * (TLEN - 1) - o;
    return o;
}

// Snapshot this lane's 3 bins of the histogram into registers.
__device__ __forceinline__ void snapshot(const int* __restrict__ h, int lane,
                                         int& s0, int& s1, int& s2)
{
    s0 = h[lane];
    s1 = h[lane + 32];
    s2 = (lane < NUM_LABELS - 64) ? h[lane + 64] : 0;
}

// Reduce a snapshot to the argmax label (lowest-label tie-break, matches
// jnp.argmax) and write it. Pure register/warp ops — no smem reads.
__device__ __forceinline__ void reduce_and_write(int s0, int s1, int s2,
                                                 float* __restrict__ orow,
                                                 int w, int lane)
{
    int p = (s0 << 7) | (127 - lane);
    p = max(p, (s1 << 7) | (127 - (lane + 32)));
    if (lane < NUM_LABELS - 64)
        p = max(p, (s2 << 7) | (127 - (lane + 64)));
    p = __reduce_max_sync(0xFFFFFFFFu, p);   // REDUX.MAX
    if (lane == 0) orow[w] = (float)(127 - (p & 127));
}

__global__ void __launch_bounds__(BLOCK)
label_majority_warpslide3(const int* __restrict__ lbl, float* __restrict__ out)
{
    __shared__ int hist[WARPS_PER_CTA][NUM_LABELS];

    const int lane = threadIdx.x & 31;
    const int wid  = threadIdx.x >> 5;
    const int b    = blockIdx.y;
    const int run  = blockIdx.x * WARPS_PER_CTA + wid;
    if (run >= RUNS_PER_B) return;

    const int w0 = run * W_RUN;

    const int* __restrict__ row  = lbl + (size_t)b * TLEN;
    float* __restrict__     orow = out + (size_t)b * NOUT;
    int* __restrict__       h    = hist[wid];

    // zero private histogram
    h[lane] = 0;
    h[lane + 32] = 0;
    if (lane < NUM_LABELS - 64) h[lane + 64] = 0;
    __syncwarp();

    if (run >= RUN_INT_LO && run <= RUN_INT_HI) {
        // ================= interior fast path ===============================
        const int* __restrict__ base = row + (w0 * HOP - PAD);  // int4-aligned

        // ---- build window w0: 8 x int4 per lane (high MLP), 32 atomics ----
        int4 v[8];
        #pragma unroll
        for (int k = 0; k < 8; k++)
            v[k] = *(const int4*)(base + k * 128 + lane * 4);
        #pragma unroll
        for (int k = 0; k < 8; k++) {
            atomicAdd(&h[v[k].x], 1);
            atomicAdd(&h[v[k].y], 1);
            atomicAdd(&h[v[k].z], 1);
            atomicAdd(&h[v[k].w], 1);
        }
        __syncwarp();

        int s0, s1, s2;
        snapshot(h, lane, s0, s1, s2);   // state of window w0

        #pragma unroll
        for (int i = 1; i < W_RUN; i++) {
            const int* __restrict__ ob = base + (i - 1) * HOP;  // leaving
            const int* __restrict__ nb = ob + FFT;              // entering
            int4 o4 = *(const int4*)(ob + lane * 4);
            int  os = ob[128 + lane];
            int4 n4 = *(const int4*)(nb + lane * 4);
            int  ns = nb[128 + lane];

            __syncwarp();   // all snapshots taken before mutating hist

            // updates for window w0+i (chain) — the reduction of the previous
            // snapshot below is register-only and overlaps with these atomics
            atomicSub(&h[o4.x], 1); atomicSub(&h[o4.y], 1);
            atomicSub(&h[o4.z], 1); atomicSub(&h[o4.w], 1);
            atomicSub(&h[os], 1);
            atomicAdd(&h[n4.x], 1); atomicAdd(&h[n4.y], 1);
            atomicAdd(&h[n4.z], 1); atomicAdd(&h[n4.w], 1);
            atomicAdd(&h[ns], 1);

            reduce_and_write(s0, s1, s2, orow, w0 + i - 1, lane);

            __syncwarp();   // updates visible
            snapshot(h, lane, s0, s1, s2);   // state of window w0+i
        }
        reduce_and_write(s0, s1, s2, orow, w0 + W_RUN - 1, lane);
    } else {
        // ================= edge path (reflect handling, scalar) ============
        const int start = w0 * HOP;
        #pragma unroll
        for (int k = 0; k < FFT / 32; k++) {
            int j = start + lane + k * 32;
            atomicAdd(&h[row[reflect_idx(j)]], 1);
        }
        __syncwarp();
        int s0, s1, s2;
        snapshot(h, lane, s0, s1, s2);
        reduce_and_write(s0, s1, s2, orow, w0, lane);

        #pragma unroll
        for (int i = 1; i < W_RUN; i++) {
            const int w = w0 + i;
            if (w >= NOUT) break;
            __syncwarp();
            const int bidx = (w - 1) * HOP;
            #pragma unroll
            for (int k = 0; k < HOP / 32; k++) {
                int jo = bidx + lane + k * 32;
                int jn = bidx + FFT + lane + k * 32;
                atomicSub(&h[row[reflect_idx(jo)]], 1);
                atomicAdd(&h[row[reflect_idx(jn)]], 1);
            }
            __syncwarp();
            snapshot(h, lane, s0, s1, s2);
            reduce_and_write(s0, s1, s2, orow, w, lane);
        }
    }
}

extern "C" void kernel_launch(void* const* d_in, const int* in_sizes, int n_in,
                              void* d_out, int out_size)
{
    const int* lbl = (const int*)d_in[0];   // [B, T] int32
    // d_in[1]: all-ones conv weight — irrelevant (window sum == histogram).
    float* out = (float*)d_out;             // [B, NOUT], compared as float32

    dim3 grid(CTAS_X, BATCH);
    label_majority_warpslide3<<<grid, BLOCK>>>(lbl, out);
}